// round 17
// baseline (speedup 1.0000x reference)
#include <cuda_runtime.h>
#include <cstdint>

#define NN   50000
#define EE   800000
#define FIN  128
#define HID  64
#define OUTC 64
#define NG   512

#define SCB  256
#define NSB  ((NN + SCB - 1) / SCB)

// ---------------- scratch ----------------
__device__ __align__(16) float d_hW  [NN * HID];
__device__ __align__(16) float d_dis [NN];
__device__ __align__(16) float d_g1  [NN * HID];
__device__ __align__(16) float d_h2  [NN * 2 * HID];
__device__ __align__(16) float d_als2[NN * 2];
__device__ __align__(16) float d_ald2[NN * 2];
__device__ __align__(16) float d_g2  [NN * 2 * HID];
__device__ __align__(16) float d_h3  [NN * OUTC];
__device__ __align__(16) float d_als3[NN];
__device__ __align__(16) float d_ald3[NN];
__device__ __align__(16) float d_pool[NG * OUTC];
__device__ __align__(16) float d_cnt [NG];

__device__ int d_fmt;
__device__ int d_bat [NN];
__device__ int d_rowptr[NN + 1];
__device__ int d_cursor[NN];
__device__ int d_csrc[EE];
__device__ int d_part[NSB];

// ---------------- helpers ----------------
__device__ __forceinline__ float lrelu(float x) { return x > 0.f ? x : 0.2f * x; }
__device__ __forceinline__ float wmax(float v) {
#pragma unroll
    for (int off = 16; off; off >>= 1) v = fmaxf(v, __shfl_xor_sync(~0u, v, off));
    return v;
}
__device__ __forceinline__ float wsum(float v) {
#pragma unroll
    for (int off = 16; off; off >>= 1) v += __shfl_xor_sync(~0u, v, off);
    return v;
}

// ---------------- init: zero + fused index-width detection ----------------
__global__ void k_init(const unsigned* __restrict__ ei_words) {
    int i = blockIdx.x * blockDim.x + threadIdx.x;
    if (i < NN) d_cursor[i] = 0;
    if (i < NG) d_cnt[i] = 0.f;
    if (i < NG * OUTC / 4) ((float4*)d_pool)[i] = make_float4(0.f, 0.f, 0.f, 0.f);
    if (blockIdx.x == 0 && threadIdx.x < 32) {
        int t = threadIdx.x;
        unsigned v = 0;
#pragma unroll
        for (int k = 0; k < 8; k++) v |= ei_words[2 * (t + 32 * k) + 1];
        unsigned any = __ballot_sync(~0u, v != 0u);
        if (t == 0) d_fmt = (any == 0u) ? 1 : 0;
    }
}

// histogram (+ batch conversion); no src/dst materialization
__global__ void k_hist(const void* __restrict__ ei, const void* __restrict__ bat) {
    int i = blockIdx.x * blockDim.x + threadIdx.x;
    int fmt = d_fmt;
    if (i < EE) {
        int d = fmt ? (int)((const long long*)ei)[EE + i] : ((const int*)ei)[EE + i];
        atomicAdd(&d_cursor[d], 1);
    }
    if (i < NN)
        d_bat[i] = fmt ? (int)((const long long*)bat)[i] : ((const int*)bat)[i];
}

// ---- parallel exclusive scan (3 phases) ----
__global__ void k_blocksum() {
    __shared__ int sh[SCB];
    int t = threadIdx.x, n = blockIdx.x * SCB + t;
    int c = (n < NN) ? d_cursor[n] : 0;
    sh[t] = c;
    __syncthreads();
#pragma unroll
    for (int off = SCB / 2; off; off >>= 1) {
        if (t < off) sh[t] += sh[t + off];
        __syncthreads();
    }
    if (t == 0) d_part[blockIdx.x] = sh[0];
}

__global__ void k_scanpart() {
    __shared__ int sh[SCB];
    int t = threadIdx.x;
    int v = (t < NSB) ? d_part[t] : 0;
    sh[t] = v;
    __syncthreads();
#pragma unroll
    for (int off = 1; off < SCB; off <<= 1) {
        int u = sh[t];
        int add = (t >= off) ? sh[t - off] : 0;
        __syncthreads();
        sh[t] = u + add;
        __syncthreads();
    }
    if (t < NSB) d_part[t] = sh[t] - v;
}

__global__ void k_rowptr() {
    __shared__ int sh[SCB];
    int t = threadIdx.x, n = blockIdx.x * SCB + t;
    int c = (n < NN) ? d_cursor[n] : 0;
    sh[t] = c;
    __syncthreads();
#pragma unroll
    for (int off = 1; off < SCB; off <<= 1) {
        int u = sh[t];
        int add = (t >= off) ? sh[t - off] : 0;
        __syncthreads();
        sh[t] = u + add;
        __syncthreads();
    }
    if (n < NN) {
        d_rowptr[n] = d_part[blockIdx.x] + sh[t] - c;
        d_dis[n] = rsqrtf((float)(c + 1));
        d_cursor[n] = 0;
        if (n == NN - 1) d_rowptr[NN] = EE;
    }
}

__global__ void k_scatter(const void* __restrict__ ei) {
    int e = blockIdx.x * blockDim.x + threadIdx.x;
    if (e >= EE) return;
    int fmt = d_fmt;
    int s, d;
    if (fmt) {
        s = (int)((const long long*)ei)[e];
        d = (int)((const long long*)ei)[EE + e];
    } else {
        s = ((const int*)ei)[e];
        d = ((const int*)ei)[EE + e];
    }
    int slot = d_rowptr[d] + atomicAdd(&d_cursor[d], 1);
    d_csrc[slot] = s;
}

// ---------------- register-blocked GEMM + fused attention-logit epilogue ----------------
// HEADS=0: plain GEMM. HEADS=2: MO=128, als2/ald2. HEADS=1: MO=64, als3/ald3.
template<int K, int MO, int HEADS>
__global__ void k_gemm2(const float* __restrict__ A, const float* __restrict__ W,
                        float* __restrict__ C,
                        const float* __restrict__ asrc, const float* __restrict__ adst,
                        int n) {
    constexpr int TX = MO / 4;
    constexpr int TY = 256 / TX;
    constexpr int NPB = TY * 4;
    __shared__ float Ws[K * MO];
    int tid = threadIdx.x;
    for (int i = tid; i < K * MO / 4; i += 256)
        ((float4*)Ws)[i] = ((const float4*)W)[i];
    __syncthreads();

    int tx = tid % TX, ty = tid / TX;
    int n0 = blockIdx.x * NPB + ty * 4;
    const float* Ar[4];
    bool valid[4];
#pragma unroll
    for (int r = 0; r < 4; r++) {
        int node = n0 + r;
        valid[r] = node < n;
        Ar[r] = A + (size_t)(valid[r] ? node : 0) * K;
    }
    float4 acc[4] = {};
#pragma unroll
    for (int k0 = 0; k0 < K; k0 += 4) {
        float4 w0 = *(const float4*)&Ws[(k0 + 0) * MO + tx * 4];
        float4 w1 = *(const float4*)&Ws[(k0 + 1) * MO + tx * 4];
        float4 w2 = *(const float4*)&Ws[(k0 + 2) * MO + tx * 4];
        float4 w3 = *(const float4*)&Ws[(k0 + 3) * MO + tx * 4];
#pragma unroll
        for (int r = 0; r < 4; r++) {
            float4 a = *(const float4*)(Ar[r] + k0);
            acc[r].x += a.x * w0.x + a.y * w1.x + a.z * w2.x + a.w * w3.x;
            acc[r].y += a.x * w0.y + a.y * w1.y + a.z * w2.y + a.w * w3.y;
            acc[r].z += a.x * w0.z + a.y * w1.z + a.z * w2.z + a.w * w3.z;
            acc[r].w += a.x * w0.w + a.y * w1.w + a.z * w2.w + a.w * w3.w;
        }
    }
#pragma unroll
    for (int r = 0; r < 4; r++)
        if (valid[r])
            *(float4*)&C[(size_t)(n0 + r) * MO + tx * 4] = acc[r];

    if (HEADS > 0) {
        // dot each node row with a_src / a_dst using register outputs
        float4 av = ((const float4*)asrc)[tx];
        float4 dv = ((const float4*)adst)[tx];
#pragma unroll
        for (int r = 0; r < 4; r++) {
            float ps = acc[r].x * av.x + acc[r].y * av.y + acc[r].z * av.z + acc[r].w * av.w;
            float pd = acc[r].x * dv.x + acc[r].y * dv.y + acc[r].z * dv.z + acc[r].w * dv.w;
#pragma unroll
            for (int off = 1; off < 16; off <<= 1) {
                ps += __shfl_xor_sync(~0u, ps, off);
                pd += __shfl_xor_sync(~0u, pd, off);
            }
            // HEADS==2: TX=32, lanes 0-15 head0, 16-31 head1; lanes 0 and 16 hold sums.
            // HEADS==1: TX=16, each 16-lane group is one node-row; tx==0 holds sum.
            if (HEADS == 2) {
                if ((tx & 15) == 0 && valid[r]) {
                    int h = tx >> 4;
                    d_als2[(n0 + r) * 2 + h] = ps;
                    d_ald2[(n0 + r) * 2 + h] = pd;
                }
            } else {
                if (tx == 0 && valid[r]) {
                    d_als3[n0 + r] = ps;
                    d_ald3[n0 + r] = pd;
                }
            }
        }
    }
}

// ---------------- GCN: pipelined float2 broadcast gather ----------------
__global__ void k_gcn(const float* __restrict__ b1) {
    int n = blockIdx.x * 8 + (threadIdx.x >> 5);
    int lane = threadIdx.x & 31;
    if (n >= NN) return;
    int beg = d_rowptr[n], end = d_rowptr[n + 1];
    float2 acc = make_float2(0.f, 0.f);
    int i0 = beg + lane;
    bool v0 = i0 < end;
    int s = v0 ? d_csrc[i0] : 0;
    float w = v0 ? d_dis[s] : 0.f;
    for (int base = beg; base < end; base += 32) {
        int nb = base + 32;
        int ns = 0; float nw = 0.f;
        if (nb < end) {
            int ni = nb + lane;
            bool nv = ni < end;
            ns = nv ? d_csrc[ni] : 0;
            nw = nv ? d_dis[ns] : 0.f;
        }
        int cnt = min(32, end - base);
#pragma unroll 8
        for (int j = 0; j < cnt; j++) {
            int   sj = __shfl_sync(~0u, s, j);
            float wj = __shfl_sync(~0u, w, j);
            float2 h = ((const float2*)(d_hW + (size_t)sj * 64))[lane];
            acc.x += wj * h.x;
            acc.y += wj * h.y;
        }
        s = ns; w = nw;
    }
    float dn = d_dis[n];
    float2 hn = ((const float2*)(d_hW + (size_t)n * 64))[lane];
    float2 b = ((const float2*)b1)[lane];
    float2 o;
    o.x = fmaxf(dn * (acc.x + dn * hn.x) + b.x, 0.f);
    o.y = fmaxf(dn * (acc.y + dn * hn.y) + b.y, 0.f);
    ((float2*)(d_g1 + (size_t)n * 64))[lane] = o;
}

// ---------------- GAT2: pipelined float4 broadcast, online softmax ----------------
__global__ void k_gat2(const float* __restrict__ b2) {
    int n = blockIdx.x * 8 + (threadIdx.x >> 5);
    int lane = threadIdx.x & 31;
    if (n >= NN) return;
    bool h0 = lane < 16;
    int beg = d_rowptr[n], end = d_rowptr[n + 1];
    float2 ald = *(const float2*)(d_ald2 + n * 2);
    float2 as  = *(const float2*)(d_als2 + n * 2);
    float m0 = lrelu(as.x + ald.x);
    float m1 = lrelu(as.y + ald.y);
    float4 acc = ((const float4*)(d_h2 + (size_t)n * 128))[lane];   // self (x=1)
    float den0 = 1.f, den1 = 1.f;
    int i0 = beg + lane;
    bool v0 = i0 < end;
    int s = v0 ? d_csrc[i0] : 0;
    float e0 = -1e30f, e1 = -1e30f;
    if (v0) {
        float2 a = *(const float2*)(d_als2 + s * 2);
        e0 = lrelu(a.x + ald.x);
        e1 = lrelu(a.y + ald.y);
    }
    for (int base = beg; base < end; base += 32) {
        int nb = base + 32;
        int ns = 0; float ne0 = -1e30f, ne1 = -1e30f;
        if (nb < end) {
            int ni = nb + lane;
            bool nv = ni < end;
            ns = nv ? d_csrc[ni] : 0;
            if (nv) {
                float2 a = *(const float2*)(d_als2 + ns * 2);
                ne0 = lrelu(a.x + ald.x);
                ne1 = lrelu(a.y + ald.y);
            }
        }
        float cm0 = wmax(e0), cm1 = wmax(e1);
        if (cm0 > m0 || cm1 > m1) {
            float r0 = 1.f, r1 = 1.f;
            if (cm0 > m0) { r0 = __expf(m0 - cm0); den0 *= r0; m0 = cm0; }
            if (cm1 > m1) { r1 = __expf(m1 - cm1); den1 *= r1; m1 = cm1; }
            float rs = h0 ? r0 : r1;
            acc.x *= rs; acc.y *= rs; acc.z *= rs; acc.w *= rs;
        }
        float x0 = __expf(e0 - m0);
        float x1 = __expf(e1 - m1);
        den0 += wsum(x0);
        den1 += wsum(x1);
        int cnt = min(32, end - base);
#pragma unroll 8
        for (int j = 0; j < cnt; j++) {
            int   sj = __shfl_sync(~0u, s, j);
            float xa = __shfl_sync(~0u, x0, j);
            float xb = __shfl_sync(~0u, x1, j);
            float xs = h0 ? xa : xb;
            float4 h = ((const float4*)(d_h2 + (size_t)sj * 128))[lane];
            acc.x += xs * h.x;
            acc.y += xs * h.y;
            acc.z += xs * h.z;
            acc.w += xs * h.w;
        }
        s = ns; e0 = ne0; e1 = ne1;
    }
    float inv = h0 ? (1.f / den0) : (1.f / den1);
    float4 b = ((const float4*)b2)[lane];
    float4 o;
    o.x = fmaxf(acc.x * inv + b.x, 0.f);
    o.y = fmaxf(acc.y * inv + b.y, 0.f);
    o.z = fmaxf(acc.z * inv + b.z, 0.f);
    o.w = fmaxf(acc.w * inv + b.w, 0.f);
    ((float4*)(d_g2 + (size_t)n * 128))[lane] = o;
}

// ---------------- GAT3: pipelined float2 broadcast + pool scatter ----------------
__global__ void k_gat3pool(const float* __restrict__ b3) {
    int n = blockIdx.x * 8 + (threadIdx.x >> 5);
    int lane = threadIdx.x & 31;
    if (n >= NN) return;
    int beg = d_rowptr[n], end = d_rowptr[n + 1];
    float ald = d_ald3[n];
    float m = lrelu(d_als3[n] + ald);
    float2 acc = ((const float2*)(d_h3 + (size_t)n * 64))[lane];    // self (x=1)
    float den = 1.f;
    int i0 = beg + lane;
    bool v0 = i0 < end;
    int s = v0 ? d_csrc[i0] : 0;
    float e = v0 ? lrelu(d_als3[s] + ald) : -1e30f;
    for (int base = beg; base < end; base += 32) {
        int nb = base + 32;
        int ns = 0; float ne = -1e30f;
        if (nb < end) {
            int ni = nb + lane;
            bool nv = ni < end;
            ns = nv ? d_csrc[ni] : 0;
            if (nv) ne = lrelu(d_als3[ns] + ald);
        }
        float cm = wmax(e);
        if (cm > m) { float r = __expf(m - cm); acc.x *= r; acc.y *= r; den *= r; m = cm; }
        float x = __expf(e - m);
        den += wsum(x);
        int cnt = min(32, end - base);
#pragma unroll 8
        for (int j = 0; j < cnt; j++) {
            int   sj = __shfl_sync(~0u, s, j);
            float xj = __shfl_sync(~0u, x, j);
            float2 h = ((const float2*)(d_h3 + (size_t)sj * 64))[lane];
            acc.x += xj * h.x;
            acc.y += xj * h.y;
        }
        s = ns; e = ne;
    }
    float inv = 1.f / den;
    float2 b = ((const float2*)b3)[lane];
    float o0 = acc.x * inv + b.x;
    float o1 = acc.y * inv + b.y;
    int g = d_bat[n];
    atomicAdd(&d_pool[(size_t)g * 64 + 2 * lane],     o0);
    atomicAdd(&d_pool[(size_t)g * 64 + 2 * lane + 1], o1);
    if (lane == 0) atomicAdd(&d_cnt[g], 1.0f);
}

__global__ void k_final(const float* __restrict__ Wfc, const float* __restrict__ bfc,
                        float* __restrict__ out) {
    int g = blockIdx.x * blockDim.x + threadIdx.x;
    if (g >= NG) return;
    float inv = 1.f / fmaxf(d_cnt[g], 1.f);
    float l0 = bfc[0], l1 = bfc[1];
#pragma unroll
    for (int f = 0; f < OUTC; f++) {
        float p = d_pool[g * OUTC + f] * inv;
        l0 += p * Wfc[f * 2 + 0];
        l1 += p * Wfc[f * 2 + 1];
    }
    float m = fmaxf(l0, l1);
    float lse = m + logf(expf(l0 - m) + expf(l1 - m));
    out[g * 2 + 0] = l0 - lse;
    out[g * 2 + 1] = l1 - lse;
}

// ---------------- host ----------------
extern "C" void kernel_launch(void* const* d_in, const int* in_sizes, int n_in,
                              void* d_out, int out_size) {
    const float* x    = (const float*)d_in[0];
    const void*  ei   = d_in[1];
    const void*  bat  = d_in[2];
    const float* W1   = (const float*)d_in[3];
    const float* b1   = (const float*)d_in[4];
    const float* W2   = (const float*)d_in[5];
    const float* as2  = (const float*)d_in[6];
    const float* ad2  = (const float*)d_in[7];
    const float* b2   = (const float*)d_in[8];
    const float* W3   = (const float*)d_in[9];
    const float* as3  = (const float*)d_in[10];
    const float* ad3  = (const float*)d_in[11];
    const float* b3   = (const float*)d_in[12];
    const float* Wfc  = (const float*)d_in[13];
    const float* bfc  = (const float*)d_in[14];
    float* out = (float*)d_out;

    void *p_hW, *p_g1, *p_g2, *p_h2, *p_h3;
    cudaGetSymbolAddress(&p_hW, d_hW);
    cudaGetSymbolAddress(&p_g1, d_g1);
    cudaGetSymbolAddress(&p_h2, d_h2);
    cudaGetSymbolAddress(&p_g2, d_g2);
    cudaGetSymbolAddress(&p_h3, d_h3);

    // init + CSR build
    k_init<<<(NN + 255) / 256, 256>>>((const unsigned*)ei);
    k_hist<<<(EE + 255) / 256, 256>>>(ei, bat);
    k_blocksum<<<NSB, SCB>>>();
    k_scanpart<<<1, SCB>>>();
    k_rowptr<<<NSB, SCB>>>();
    k_scatter<<<(EE + 255) / 256, 256>>>(ei);

    // GCN
    k_gemm2<128, 64, 0><<<(NN + 63) / 64, 256>>>(x, W1, (float*)p_hW, nullptr, nullptr, NN);
    k_gcn<<<(NN + 7) / 8, 256>>>(b1);

    // GAT layer 2 (logits fused in GEMM epilogue)
    k_gemm2<64, 128, 2><<<(NN + 31) / 32, 256>>>((const float*)p_g1, W2, (float*)p_h2, as2, ad2, NN);
    k_gat2<<<(NN + 7) / 8, 256>>>(b2);

    // GAT layer 3 (logits fused in GEMM epilogue)
    k_gemm2<128, 64, 1><<<(NN + 63) / 64, 256>>>((const float*)p_g2, W3, (float*)p_h3, as3, ad3, NN);
    k_gat3pool<<<(NN + 7) / 8, 256>>>(b3);

    // pooled @ Wfc + log_softmax
    k_final<<<(NG + 255) / 256, 256>>>(Wfc, bfc, out);
}